// round 7
// baseline (speedup 1.0000x reference)
#include <cuda_runtime.h>

#define N_NODES 100000
#define N_EDGES 100000
#define N_PINS  1600000
#define IN_DIM  32
#define HID     64
#define NEG     0.01f
#define NB      391           // ceil(100000/256)

__device__ __forceinline__ float leaky(float v) { return v >= 0.f ? v : NEG * v; }

// f32x2 packed-FMA helpers (Blackwell FFMA2 — only reachable via PTX)
__device__ __forceinline__ unsigned long long pack2(float lo, float hi) {
    unsigned long long r;
    asm("mov.b64 %0, {%1,%2};" : "=l"(r) : "f"(lo), "f"(hi));
    return r;
}
__device__ __forceinline__ void fma2(unsigned long long& d,
                                     unsigned long long a, unsigned long long b) {
    asm("fma.rn.f32x2 %0, %1, %2, %0;" : "+l"(d) : "l"(a), "l"(b));
}
__device__ __forceinline__ float2 unpack2(unsigned long long v) {
    float2 r;
    asm("mov.b64 {%0,%1}, %2;" : "=f"(r.x), "=f"(r.y) : "l"(v));
    return r;
}

// ---------------- scratch: __device__ globals ---------------------------------
__device__ __align__(16) float g_HE [N_EDGES * HID];   // edge-gather result
__device__ __align__(16) float g_G  [N_NODES * HID];   // node-gather result
__device__ __align__(16) float g_H  [N_NODES * HID];   // hidden state
__device__ __align__(16) float g_MU [N_NODES * HID];   // mu
__device__ __align__(16) float g_dvec[N_NODES];
__device__ float g_sumsq;

// CSR
__device__ int g_ecnt [N_EDGES];
__device__ int g_ncnt [N_NODES];
__device__ int g_estart[N_EDGES + 1];
__device__ int g_nstart[N_NODES + 1];
__device__ int g_epins[N_PINS];   // node ids grouped by edge
__device__ int g_npins[N_PINS];   // edge ids grouped by node
__device__ int g_bsum_e[NB];
__device__ int g_bsum_n[NB];

// ---------------- CSR build ----------------------------------------------------
__global__ void zero_cnt_kernel() {
    int i = blockIdx.x * blockDim.x + threadIdx.x;
    if (i < N_EDGES) g_ecnt[i] = 0;
    if (i < N_NODES) g_ncnt[i] = 0;
    if (i == 0) g_sumsq = 0.f;
}

__global__ void hist_kernel(const int* __restrict__ nidx, const int* __restrict__ eidx) {
    int i = blockIdx.x * blockDim.x + threadIdx.x;
    if (i < N_PINS) {
        atomicAdd(&g_ncnt[nidx[i]], 1);
        atomicAdd(&g_ecnt[eidx[i]], 1);
    }
}

__global__ void scan1_kernel() {
    __shared__ int se[256], sn[256];
    int tid = threadIdx.x;
    int gid = blockIdx.x * 256 + tid;
    se[tid] = (gid < N_EDGES) ? g_ecnt[gid] : 0;
    sn[tid] = (gid < N_NODES) ? g_ncnt[gid] : 0;
    __syncthreads();
    for (int off = 128; off > 0; off >>= 1) {
        if (tid < off) { se[tid] += se[tid + off]; sn[tid] += sn[tid + off]; }
        __syncthreads();
    }
    if (tid == 0) { g_bsum_e[blockIdx.x] = se[0]; g_bsum_n[blockIdx.x] = sn[0]; }
}

__global__ void scan2_kernel() {
    __shared__ int se[512], sn[512];
    int tid = threadIdx.x;
    int ve = (tid < NB) ? g_bsum_e[tid] : 0;
    int vn = (tid < NB) ? g_bsum_n[tid] : 0;
    se[tid] = ve; sn[tid] = vn;
    __syncthreads();
    for (int off = 1; off < 512; off <<= 1) {
        int ae = (tid >= off) ? se[tid - off] : 0;
        int an = (tid >= off) ? sn[tid - off] : 0;
        __syncthreads();
        se[tid] += ae; sn[tid] += an;
        __syncthreads();
    }
    if (tid < NB) { g_bsum_e[tid] = se[tid] - ve; g_bsum_n[tid] = sn[tid] - vn; }
    if (tid == 0) { g_estart[N_EDGES] = N_PINS; g_nstart[N_NODES] = N_PINS; }
}

__global__ void scan3_kernel() {
    __shared__ int se[256], sn[256];
    int tid = threadIdx.x;
    int gid = blockIdx.x * 256 + tid;
    int ve = (gid < N_EDGES) ? g_ecnt[gid] : 0;
    int vn = (gid < N_NODES) ? g_ncnt[gid] : 0;
    se[tid] = ve; sn[tid] = vn;
    __syncthreads();
    for (int off = 1; off < 256; off <<= 1) {
        int ae = (tid >= off) ? se[tid - off] : 0;
        int an = (tid >= off) ? sn[tid - off] : 0;
        __syncthreads();
        se[tid] += ae; sn[tid] += an;
        __syncthreads();
    }
    if (gid < N_EDGES) { g_estart[gid] = g_bsum_e[blockIdx.x] + se[tid] - ve; g_ecnt[gid] = 0; }
    if (gid < N_NODES) { g_nstart[gid] = g_bsum_n[blockIdx.x] + sn[tid] - vn; g_ncnt[gid] = 0; }
}

__global__ void fill_kernel(const int* __restrict__ nidx, const int* __restrict__ eidx) {
    int i = blockIdx.x * blockDim.x + threadIdx.x;
    if (i >= N_PINS) return;
    int n = nidx[i], e = eidx[i];
    int pe = g_estart[e] + atomicAdd(&g_ecnt[e], 1);
    g_epins[pe] = n;
    int pn = g_nstart[n] + atomicAdd(&g_ncnt[n], 1);
    g_npins[pn] = e;
}

// ---------------- gather: dst[row] = (1/deg) * sum_{p in row} src[pin_p] ------
// One warp per row; lane owns a float4 column slice; unroll-2 for 2x MLP.
// SIDE 0: edge side (dst=g_HE). SIDE 1: node side (dst=g_G).
// SRCSEL 0: param Xp. 1: g_HE. 2: g_H.
template <int W, int SIDE, int SRCSEL>
__global__ __launch_bounds__(256) void gather_kernel(const float* __restrict__ Xp) {
    constexpr int LPR = W / 4;     // lanes per pin-row: 8 (W=32) / 16 (W=64)
    constexpr int PPW = 32 / LPR;  // pins in parallel:   4 / 2
    int row  = (blockIdx.x * blockDim.x + threadIdx.x) >> 5;
    int lane = threadIdx.x & 31;
    if (row >= N_NODES) return;    // N_NODES == N_EDGES
    const int* start = (SIDE == 0) ? g_estart : g_nstart;
    const int* pins  = (SIDE == 0) ? g_epins  : g_npins;
    const float* src = (SRCSEL == 0) ? Xp : (SRCSEL == 1) ? g_HE : g_H;
    float* dst = (SIDE == 0) ? g_HE : g_G;
    int sub = lane / LPR;
    int c4  = (lane % LPR) << 2;
    int s = start[row], e = start[row + 1];
    float ax0=0.f, ay0=0.f, az0=0.f, aw0=0.f;
    float ax1=0.f, ay1=0.f, az1=0.f, aw1=0.f;
    int i = s + sub;
    for (; i + PPW < e; i += 2 * PPW) {
        int p0 = pins[i], p1 = pins[i + PPW];
        float4 v0 = *(const float4*)(src + (long)p0 * W + c4);
        float4 v1 = *(const float4*)(src + (long)p1 * W + c4);
        ax0 += v0.x; ay0 += v0.y; az0 += v0.z; aw0 += v0.w;
        ax1 += v1.x; ay1 += v1.y; az1 += v1.z; aw1 += v1.w;
    }
    if (i < e) {
        int p = pins[i];
        float4 v = *(const float4*)(src + (long)p * W + c4);
        ax0 += v.x; ay0 += v.y; az0 += v.z; aw0 += v.w;
    }
    ax0 += ax1; ay0 += ay1; az0 += az1; aw0 += aw1;
    #pragma unroll
    for (int off = LPR; off < 32; off <<= 1) {
        ax0 += __shfl_xor_sync(0xffffffffu, ax0, off);
        ay0 += __shfl_xor_sync(0xffffffffu, ay0, off);
        az0 += __shfl_xor_sync(0xffffffffu, az0, off);
        aw0 += __shfl_xor_sync(0xffffffffu, aw0, off);
    }
    if (lane < LPR) {
        float inv = (e > s) ? 1.0f / (float)(e - s) : 0.0f;
        float4 r = make_float4(ax0 * inv, ay0 * inv, az0 * inv, aw0 * inv);
        *(float4*)(dst + (long)row * W + c4) = r;
    }
}

// ---------------- matmul v2: FFMA2, 64 rows/block, 2r x 8c per thread ---------
// out[N,64] = epi(g_G[N,K] @ Wm[K,64] + bias)
// EPI: 0 none, 1 leaky, 2 layernorm(g,be)+leaky.  DST: 0 g_H, 1 g_MU, 2 outp.
template <int K, int EPI, int DST>
__global__ __launch_bounds__(256) void matmul2_kernel(
    const float* __restrict__ Wm, const float* __restrict__ bias,
    const float* __restrict__ gg, const float* __restrict__ be,
    float* __restrict__ outp)
{
    __shared__ __align__(16) float Ws[K * 64];
    __shared__ float Xs[64][K + 1];
    int tid = threadIdx.x;
    for (int i = tid; i < K * 16; i += 256)
        *(float4*)&Ws[i * 4] = *(const float4*)&Wm[i * 4];
    int node0 = blockIdx.x * 64;
    int limit = N_NODES - node0;           // valid rows in this block
    for (int idx = tid; idx < 16 * K; idx += 256) {
        int flat = idx * 4;
        int r = flat / K, c = flat & (K - 1);
        float4 v = make_float4(0.f, 0.f, 0.f, 0.f);
        if (r < limit) v = *(const float4*)&g_G[(long)(node0 + r) * K + c];
        Xs[r][c] = v.x; Xs[r][c+1] = v.y; Xs[r][c+2] = v.z; Xs[r][c+3] = v.w;
    }
    __syncthreads();
    int j0 = (tid & 7) << 3;     // 8 col-groups of 8
    int r0 = (tid >> 3) << 1;    // 2 rows each, 64 rows
    unsigned long long acc[2][4] = {};
    #pragma unroll
    for (int k = 0; k < K; k++) {
        float xs0 = Xs[r0][k], xs1 = Xs[r0 + 1][k];
        unsigned long long x0 = pack2(xs0, xs0);
        unsigned long long x1 = pack2(xs1, xs1);
        ulonglong2 wA = *(const ulonglong2*)&Ws[k * 64 + j0];
        ulonglong2 wB = *(const ulonglong2*)&Ws[k * 64 + j0 + 4];
        fma2(acc[0][0], x0, wA.x); fma2(acc[0][1], x0, wA.y);
        fma2(acc[0][2], x0, wB.x); fma2(acc[0][3], x0, wB.y);
        fma2(acc[1][0], x1, wA.x); fma2(acc[1][1], x1, wA.y);
        fma2(acc[1][2], x1, wB.x); fma2(acc[1][3], x1, wB.y);
    }
    float bb[8];
    *(float4*)&bb[0] = *(const float4*)&bias[j0];
    *(float4*)&bb[4] = *(const float4*)&bias[j0 + 4];
    float v[2][8];
    #pragma unroll
    for (int rr = 0; rr < 2; rr++) {
        #pragma unroll
        for (int q = 0; q < 4; q++) {
            float2 p = unpack2(acc[rr][q]);
            v[rr][2*q]   = p.x + bb[2*q];
            v[rr][2*q+1] = p.y + bb[2*q+1];
        }
    }
    if (EPI == 1) {
        #pragma unroll
        for (int rr = 0; rr < 2; rr++)
            #pragma unroll
            for (int c = 0; c < 8; c++) v[rr][c] = leaky(v[rr][c]);
    }
    if (EPI == 2) {
        float gv[8], ev[8];
        *(float4*)&gv[0] = *(const float4*)&gg[j0];
        *(float4*)&gv[4] = *(const float4*)&gg[j0 + 4];
        *(float4*)&ev[0] = *(const float4*)&be[j0];
        *(float4*)&ev[4] = *(const float4*)&be[j0 + 4];
        #pragma unroll
        for (int rr = 0; rr < 2; rr++) {
            float s = 0.f, sq = 0.f;
            #pragma unroll
            for (int c = 0; c < 8; c++) { s += v[rr][c]; sq += v[rr][c] * v[rr][c]; }
            #pragma unroll
            for (int off = 1; off < 8; off <<= 1) {
                s  += __shfl_xor_sync(0xffffffffu, s,  off);
                sq += __shfl_xor_sync(0xffffffffu, sq, off);
            }
            float mean = s * (1.0f / 64.0f);
            float var  = sq * (1.0f / 64.0f) - mean * mean;
            float rstd = rsqrtf(var + 1e-5f);
            #pragma unroll
            for (int c = 0; c < 8; c++)
                v[rr][c] = leaky((v[rr][c] - mean) * rstd * gv[c] + ev[c]);
        }
    }
    float* out = (DST == 0) ? g_H : (DST == 1) ? g_MU : outp;
    #pragma unroll
    for (int rr = 0; rr < 2; rr++) {
        int r = r0 + rr;
        if (r < limit) {
            long off = (long)(node0 + r) * 64 + j0;
            *(float4*)&out[off]     = make_float4(v[rr][0], v[rr][1], v[rr][2], v[rr][3]);
            *(float4*)&out[off + 4] = make_float4(v[rr][4], v[rr][5], v[rr][6], v[rr][7]);
        }
    }
}

// ---------------- decoder: 64 -> 32 -> 8 -> 1 + sumsq -------------------------
__global__ void decode_kernel(const float* __restrict__ dW1, const float* __restrict__ db1,
                              const float* __restrict__ dW2, const float* __restrict__ db2,
                              const float* __restrict__ dW3, const float* __restrict__ db3) {
    __shared__ float W1s[64 * 32];
    __shared__ float W2s[32 * 8];
    __shared__ float W3s[8];
    __shared__ float b1s[32], b2s[8], b3s;
    __shared__ float mus[4][64];
    __shared__ float v1s[4][32];
    __shared__ float v2s[4][8];
    __shared__ float dsq[4];
    int tid = threadIdx.x;  // 128
    for (int i = tid; i < 2048; i += 128) W1s[i] = dW1[i];
    for (int i = tid; i < 256;  i += 128) W2s[i] = dW2[i];
    if (tid < 8)  W3s[tid] = dW3[tid];
    if (tid < 32) b1s[tid] = db1[tid];
    if (tid >= 32 && tid < 40) b2s[tid - 32] = db2[tid - 32];
    if (tid == 40) b3s = db3[0];
    int w = tid >> 5, lane = tid & 31;
    int node = blockIdx.x * 4 + w;
    bool active = node < N_NODES;
    if (active) {
        mus[w][lane]      = g_MU[(long)node * 64 + lane];
        mus[w][lane + 32] = g_MU[(long)node * 64 + lane + 32];
    }
    __syncthreads();
    float d = 0.f;
    if (active) {
        float a1 = b1s[lane];
        #pragma unroll
        for (int k = 0; k < 64; k++) a1 += mus[w][k] * W1s[k * 32 + lane];
        v1s[w][lane] = leaky(a1);
        __syncwarp();
        if (lane < 8) {
            float a2 = b2s[lane];
            #pragma unroll
            for (int k = 0; k < 32; k++) a2 += v1s[w][k] * W2s[k * 8 + lane];
            v2s[w][lane] = leaky(a2);
        }
        __syncwarp();
        if (lane == 0) {
            d = b3s;
            #pragma unroll
            for (int o = 0; o < 8; o++) d += v2s[w][o] * W3s[o];
            g_dvec[node] = d;
        }
    }
    if (lane == 0) dsq[w] = active ? d * d : 0.f;
    __syncthreads();
    if (tid == 0) atomicAdd(&g_sumsq, dsq[0] + dsq[1] + dsq[2] + dsq[3]);
}

__global__ void norm_write_kernel(float* __restrict__ oz, float* __restrict__ om) {
    int i = blockIdx.x * blockDim.x + threadIdx.x;
    if (i >= N_NODES) return;
    float sc = 1.0f / fmaxf(sqrtf(g_sumsq), 1e-8f);
    float v = g_dvec[i] * sc;
    oz[i] = v;
    om[i] = v;
}

// ---------------- host launch ---------------------------------------------------
extern "C" void kernel_launch(void* const* d_in, const int* in_sizes, int n_in,
                              void* d_out, int out_size) {
    const float* x   = (const float*)d_in[0];
    const int*   hei = (const int*)d_in[1];   // int32 (JAX x64 disabled)
    const float *W1 = (const float*)d_in[2],  *b1  = (const float*)d_in[3];
    const float *g1 = (const float*)d_in[4],  *be1 = (const float*)d_in[5];
    const float *W2 = (const float*)d_in[6],  *b2  = (const float*)d_in[7];
    const float *Wmu= (const float*)d_in[8],  *bmu = (const float*)d_in[9];
    const float *Wlv= (const float*)d_in[10], *blv = (const float*)d_in[11];
    const float *dW1= (const float*)d_in[12], *db1 = (const float*)d_in[13];
    const float *dW2= (const float*)d_in[14], *db2 = (const float*)d_in[15];
    const float *dW3= (const float*)d_in[16], *db3 = (const float*)d_in[17];

    const int* nidx = hei;
    const int* eidx = hei + N_PINS;

    float* out    = (float*)d_out;
    float* out_z  = out;
    float* out_m  = out + N_NODES;
    float* out_lv = out + 2 * N_NODES;

    const int TB = 256;
    const int pins_blocks   = (N_PINS + TB - 1) / TB;      // 6250
    const int gather_blocks = (N_NODES * 32) / TB;         // 12500 (warp/row)
    const int mm_blocks     = (N_NODES + 63) / 64;         // 1563
    const int dec_blocks    = (N_NODES + 3) / 4;
    const int n_blocks      = (N_NODES + TB - 1) / TB;

    // CSR build
    zero_cnt_kernel<<<NB, TB>>>();
    hist_kernel<<<pins_blocks, TB>>>(nidx, eidx);
    scan1_kernel<<<NB, TB>>>();
    scan2_kernel<<<1, 512>>>();
    scan3_kernel<<<NB, TB>>>();
    fill_kernel<<<pins_blocks, TB>>>(nidx, eidx);

    // layer 1: gather(x) (32-wide) -> @W1+b1 -> LN -> leaky -> g_H
    gather_kernel<32, 0, 0><<<gather_blocks, TB>>>(x);
    gather_kernel<32, 1, 1><<<gather_blocks, TB>>>(nullptr);
    matmul2_kernel<32, 2, 0><<<mm_blocks, TB>>>(W1, b1, g1, be1, nullptr);

    // layer 2: gather(g_H) -> @W2+b2 -> leaky -> g_H
    gather_kernel<64, 0, 2><<<gather_blocks, TB>>>(nullptr);
    gather_kernel<64, 1, 1><<<gather_blocks, TB>>>(nullptr);
    matmul2_kernel<64, 1, 0><<<mm_blocks, TB>>>(W2, b2, nullptr, nullptr, nullptr);

    // mu / logvar share one gathered tensor (g_G read twice, cheap)
    gather_kernel<64, 0, 2><<<gather_blocks, TB>>>(nullptr);
    gather_kernel<64, 1, 1><<<gather_blocks, TB>>>(nullptr);
    matmul2_kernel<64, 0, 1><<<mm_blocks, TB>>>(Wmu, bmu, nullptr, nullptr, nullptr);
    matmul2_kernel<64, 0, 2><<<mm_blocks, TB>>>(Wlv, blv, nullptr, nullptr, out_lv);

    // decode(z = mu) once; z_orth == mu_orth in eval mode
    decode_kernel<<<dec_blocks, 128>>>(dW1, db1, dW2, db2, dW3, db3);
    norm_write_kernel<<<n_blocks, TB>>>(out_z, out_m);
}

// round 8
// speedup vs baseline: 1.0425x; 1.0425x over previous
#include <cuda_runtime.h>

#define N_NODES 100000
#define N_EDGES 100000
#define N_PINS  1600000
#define IN_DIM  32
#define HID     64
#define NEG     0.01f
#define NB      391           // ceil(100000/256)

__device__ __forceinline__ float leaky(float v) { return v >= 0.f ? v : NEG * v; }

// f32x2 packed-FMA helpers (Blackwell FFMA2 — only reachable via PTX)
__device__ __forceinline__ unsigned long long pack2(float lo, float hi) {
    unsigned long long r;
    asm("mov.b64 %0, {%1,%2};" : "=l"(r) : "f"(lo), "f"(hi));
    return r;
}
__device__ __forceinline__ void fma2(unsigned long long& d,
                                     unsigned long long a, unsigned long long b) {
    asm("fma.rn.f32x2 %0, %1, %2, %0;" : "+l"(d) : "l"(a), "l"(b));
}
__device__ __forceinline__ float2 unpack2(unsigned long long v) {
    float2 r;
    asm("mov.b64 {%0,%1}, %2;" : "=f"(r.x), "=f"(r.y) : "l"(v));
    return r;
}

// ---------------- scratch: __device__ globals ---------------------------------
__device__ __align__(16) float g_HE [N_EDGES * HID];   // edge-gather result
__device__ __align__(16) float g_G  [N_NODES * HID];   // node-gather result
__device__ __align__(16) float g_H  [N_NODES * HID];   // hidden state
__device__ __align__(16) float g_MU [N_NODES * HID];   // mu
__device__ __align__(16) float g_dvec[N_NODES];
__device__ float g_sumsq;

// CSR
__device__ int g_ecnt [N_EDGES];
__device__ int g_ncnt [N_NODES];
__device__ int g_estart[N_EDGES + 1];
__device__ int g_nstart[N_NODES + 1];
__device__ int g_epins[N_PINS];   // node ids grouped by edge
__device__ int g_npins[N_PINS];   // edge ids grouped by node
__device__ int g_bsum_e[NB];
__device__ int g_bsum_n[NB];

// ---------------- CSR build ----------------------------------------------------
__global__ void zero_cnt_kernel() {
    int i = blockIdx.x * blockDim.x + threadIdx.x;
    if (i < N_EDGES) g_ecnt[i] = 0;
    if (i < N_NODES) g_ncnt[i] = 0;
    if (i == 0) g_sumsq = 0.f;
}

__global__ void hist_kernel(const int* __restrict__ nidx, const int* __restrict__ eidx) {
    int i = blockIdx.x * blockDim.x + threadIdx.x;
    if (i < N_PINS) {
        atomicAdd(&g_ncnt[nidx[i]], 1);
        atomicAdd(&g_ecnt[eidx[i]], 1);
    }
}

__global__ void scan1_kernel() {
    __shared__ int se[256], sn[256];
    int tid = threadIdx.x;
    int gid = blockIdx.x * 256 + tid;
    se[tid] = (gid < N_EDGES) ? g_ecnt[gid] : 0;
    sn[tid] = (gid < N_NODES) ? g_ncnt[gid] : 0;
    __syncthreads();
    for (int off = 128; off > 0; off >>= 1) {
        if (tid < off) { se[tid] += se[tid + off]; sn[tid] += sn[tid + off]; }
        __syncthreads();
    }
    if (tid == 0) { g_bsum_e[blockIdx.x] = se[0]; g_bsum_n[blockIdx.x] = sn[0]; }
}

__global__ void scan2_kernel() {
    __shared__ int se[512], sn[512];
    int tid = threadIdx.x;
    int ve = (tid < NB) ? g_bsum_e[tid] : 0;
    int vn = (tid < NB) ? g_bsum_n[tid] : 0;
    se[tid] = ve; sn[tid] = vn;
    __syncthreads();
    for (int off = 1; off < 512; off <<= 1) {
        int ae = (tid >= off) ? se[tid - off] : 0;
        int an = (tid >= off) ? sn[tid - off] : 0;
        __syncthreads();
        se[tid] += ae; sn[tid] += an;
        __syncthreads();
    }
    if (tid < NB) { g_bsum_e[tid] = se[tid] - ve; g_bsum_n[tid] = sn[tid] - vn; }
    if (tid == 0) { g_estart[N_EDGES] = N_PINS; g_nstart[N_NODES] = N_PINS; }
}

__global__ void scan3_kernel() {
    __shared__ int se[256], sn[256];
    int tid = threadIdx.x;
    int gid = blockIdx.x * 256 + tid;
    int ve = (gid < N_EDGES) ? g_ecnt[gid] : 0;
    int vn = (gid < N_NODES) ? g_ncnt[gid] : 0;
    se[tid] = ve; sn[tid] = vn;
    __syncthreads();
    for (int off = 1; off < 256; off <<= 1) {
        int ae = (tid >= off) ? se[tid - off] : 0;
        int an = (tid >= off) ? sn[tid - off] : 0;
        __syncthreads();
        se[tid] += ae; sn[tid] += an;
        __syncthreads();
    }
    if (gid < N_EDGES) { g_estart[gid] = g_bsum_e[blockIdx.x] + se[tid] - ve; g_ecnt[gid] = 0; }
    if (gid < N_NODES) { g_nstart[gid] = g_bsum_n[blockIdx.x] + sn[tid] - vn; g_ncnt[gid] = 0; }
}

__global__ void fill_kernel(const int* __restrict__ nidx, const int* __restrict__ eidx) {
    int i = blockIdx.x * blockDim.x + threadIdx.x;
    if (i >= N_PINS) return;
    int n = nidx[i], e = eidx[i];
    int pe = g_estart[e] + atomicAdd(&g_ecnt[e], 1);
    g_epins[pe] = n;
    int pn = g_nstart[n] + atomicAdd(&g_ncnt[n], 1);
    g_npins[pn] = e;
}

// ---------------- gather (exact Round-6 form: throughput-bound, leave alone) --
// One warp per row; lane owns a float4 column slice; PPW pins in flight.
// SIDE 0: edge side (dst=g_HE). SIDE 1: node side (dst=g_G).
// SRCSEL 0: param Xp. 1: g_HE. 2: g_H.
template <int W, int SIDE, int SRCSEL>
__global__ void gather_kernel(const float* __restrict__ Xp) {
    constexpr int LPR = W / 4;     // lanes per pin-row: 8 (W=32) / 16 (W=64)
    constexpr int PPW = 32 / LPR;  // pins in parallel:   4 / 2
    int row  = (blockIdx.x * blockDim.x + threadIdx.x) >> 5;
    int lane = threadIdx.x & 31;
    if (row >= N_NODES) return;    // N_NODES == N_EDGES
    const int* start = (SIDE == 0) ? g_estart : g_nstart;
    const int* pins  = (SIDE == 0) ? g_epins  : g_npins;
    const float* src = (SRCSEL == 0) ? Xp : (SRCSEL == 1) ? g_HE : g_H;
    float* dst = (SIDE == 0) ? g_HE : g_G;
    int sub = lane / LPR;
    int c4  = (lane % LPR) << 2;
    int s = start[row], e = start[row + 1];
    float ax = 0.f, ay = 0.f, az = 0.f, aw = 0.f;
    for (int i = s + sub; i < e; i += PPW) {
        int p = pins[i];
        float4 v = *(const float4*)(src + (long)p * W + c4);
        ax += v.x; ay += v.y; az += v.z; aw += v.w;
    }
    #pragma unroll
    for (int off = LPR; off < 32; off <<= 1) {
        ax += __shfl_xor_sync(0xffffffffu, ax, off);
        ay += __shfl_xor_sync(0xffffffffu, ay, off);
        az += __shfl_xor_sync(0xffffffffu, az, off);
        aw += __shfl_xor_sync(0xffffffffu, aw, off);
    }
    if (lane < LPR) {
        float inv = (e > s) ? 1.0f / (float)(e - s) : 0.0f;
        float4 r = make_float4(ax * inv, ay * inv, az * inv, aw * inv);
        *(float4*)(dst + (long)row * W + c4) = r;
    }
}

// ---------------- FFMA2 matmul: 64 rows/block, 2r x 8c per thread -------------
// out[N,64] = epi(g_G[N,K] @ Wm[K,64] + bias)
// EPI: 0 none, 1 leaky, 2 layernorm(g,be)+leaky.  DST: 0 g_H, 1 outp.
template <int K, int EPI, int DST>
__global__ __launch_bounds__(256) void matmul2_kernel(
    const float* __restrict__ Wm, const float* __restrict__ bias,
    const float* __restrict__ gg, const float* __restrict__ be,
    float* __restrict__ outp)
{
    __shared__ __align__(16) float Ws[K * 64];
    __shared__ __align__(16) float Xs[64 * K];
    int tid = threadIdx.x;
    for (int i = tid; i < K * 16; i += 256)
        *(float4*)&Ws[i * 4] = *(const float4*)&Wm[i * 4];
    int node0 = blockIdx.x * 64;
    int limit = N_NODES - node0;           // valid rows in this block
    for (int i = tid; i < 16 * K; i += 256) {
        int r = (i * 4) / K;
        float4 v = make_float4(0.f, 0.f, 0.f, 0.f);
        if (r < limit) v = *(const float4*)&g_G[(long)node0 * K + i * 4];
        *(float4*)&Xs[i * 4] = v;
    }
    __syncthreads();
    int j0 = (tid & 7) << 3;     // 8 col-groups of 8
    int r0 = (tid >> 3) << 1;    // 2 rows each, 64 rows
    unsigned long long acc[2][4] = {};
    #pragma unroll
    for (int k = 0; k < K; k++) {
        float xs0 = Xs[r0 * K + k], xs1 = Xs[(r0 + 1) * K + k];
        unsigned long long x0 = pack2(xs0, xs0);
        unsigned long long x1 = pack2(xs1, xs1);
        ulonglong2 wA = *(const ulonglong2*)&Ws[k * 64 + j0];
        ulonglong2 wB = *(const ulonglong2*)&Ws[k * 64 + j0 + 4];
        fma2(acc[0][0], x0, wA.x); fma2(acc[0][1], x0, wA.y);
        fma2(acc[0][2], x0, wB.x); fma2(acc[0][3], x0, wB.y);
        fma2(acc[1][0], x1, wA.x); fma2(acc[1][1], x1, wA.y);
        fma2(acc[1][2], x1, wB.x); fma2(acc[1][3], x1, wB.y);
    }
    float bb[8];
    *(float4*)&bb[0] = *(const float4*)&bias[j0];
    *(float4*)&bb[4] = *(const float4*)&bias[j0 + 4];
    float v[2][8];
    #pragma unroll
    for (int rr = 0; rr < 2; rr++) {
        #pragma unroll
        for (int q = 0; q < 4; q++) {
            float2 p = unpack2(acc[rr][q]);
            v[rr][2*q]   = p.x + bb[2*q];
            v[rr][2*q+1] = p.y + bb[2*q+1];
        }
    }
    if (EPI == 1) {
        #pragma unroll
        for (int rr = 0; rr < 2; rr++)
            #pragma unroll
            for (int c = 0; c < 8; c++) v[rr][c] = leaky(v[rr][c]);
    }
    if (EPI == 2) {
        float gv[8], ev[8];
        *(float4*)&gv[0] = *(const float4*)&gg[j0];
        *(float4*)&gv[4] = *(const float4*)&gg[j0 + 4];
        *(float4*)&ev[0] = *(const float4*)&be[j0];
        *(float4*)&ev[4] = *(const float4*)&be[j0 + 4];
        #pragma unroll
        for (int rr = 0; rr < 2; rr++) {
            float s = 0.f, sq = 0.f;
            #pragma unroll
            for (int c = 0; c < 8; c++) { s += v[rr][c]; sq += v[rr][c] * v[rr][c]; }
            #pragma unroll
            for (int off = 1; off < 8; off <<= 1) {
                s  += __shfl_xor_sync(0xffffffffu, s,  off);
                sq += __shfl_xor_sync(0xffffffffu, sq, off);
            }
            float mean = s * (1.0f / 64.0f);
            float var  = sq * (1.0f / 64.0f) - mean * mean;
            float rstd = rsqrtf(var + 1e-5f);
            #pragma unroll
            for (int c = 0; c < 8; c++)
                v[rr][c] = leaky((v[rr][c] - mean) * rstd * gv[c] + ev[c]);
        }
    }
    float* out = (DST == 0) ? g_H : outp;
    #pragma unroll
    for (int rr = 0; rr < 2; rr++) {
        int r = r0 + rr;
        if (r < limit) {
            long off = (long)(node0 + r) * 64 + j0;
            *(float4*)&out[off]     = make_float4(v[rr][0], v[rr][1], v[rr][2], v[rr][3]);
            *(float4*)&out[off + 4] = make_float4(v[rr][4], v[rr][5], v[rr][6], v[rr][7]);
        }
    }
}

// ---------------- dual FFMA2 matmul: mu -> g_MU, logvar -> outp (K=64) --------
__global__ __launch_bounds__(256) void matmul2_dual_kernel(
    const float* __restrict__ Wa, const float* __restrict__ ba,
    const float* __restrict__ Wb, const float* __restrict__ bb,
    float* __restrict__ outp)
{
    __shared__ __align__(16) float Wsa[64 * 64];
    __shared__ __align__(16) float Wsb[64 * 64];
    __shared__ __align__(16) float Xs[64 * 64];
    int tid = threadIdx.x;
    for (int i = tid; i < 1024; i += 256) {
        *(float4*)&Wsa[i * 4] = *(const float4*)&Wa[i * 4];
        *(float4*)&Wsb[i * 4] = *(const float4*)&Wb[i * 4];
    }
    int node0 = blockIdx.x * 64;
    int limit = N_NODES - node0;
    for (int i = tid; i < 1024; i += 256) {
        int r = (i * 4) >> 6;
        float4 v = make_float4(0.f, 0.f, 0.f, 0.f);
        if (r < limit) v = *(const float4*)&g_G[(long)node0 * 64 + i * 4];
        *(float4*)&Xs[i * 4] = v;
    }
    __syncthreads();
    int j0 = (tid & 7) << 3;
    int r0 = (tid >> 3) << 1;
    unsigned long long accA[2][4] = {}, accB[2][4] = {};
    #pragma unroll
    for (int k = 0; k < 64; k++) {
        float xs0 = Xs[r0 * 64 + k], xs1 = Xs[(r0 + 1) * 64 + k];
        unsigned long long x0 = pack2(xs0, xs0);
        unsigned long long x1 = pack2(xs1, xs1);
        ulonglong2 aA = *(const ulonglong2*)&Wsa[k * 64 + j0];
        ulonglong2 aB = *(const ulonglong2*)&Wsa[k * 64 + j0 + 4];
        ulonglong2 bA = *(const ulonglong2*)&Wsb[k * 64 + j0];
        ulonglong2 bB = *(const ulonglong2*)&Wsb[k * 64 + j0 + 4];
        fma2(accA[0][0], x0, aA.x); fma2(accA[0][1], x0, aA.y);
        fma2(accA[0][2], x0, aB.x); fma2(accA[0][3], x0, aB.y);
        fma2(accA[1][0], x1, aA.x); fma2(accA[1][1], x1, aA.y);
        fma2(accA[1][2], x1, aB.x); fma2(accA[1][3], x1, aB.y);
        fma2(accB[0][0], x0, bA.x); fma2(accB[0][1], x0, bA.y);
        fma2(accB[0][2], x0, bB.x); fma2(accB[0][3], x0, bB.y);
        fma2(accB[1][0], x1, bA.x); fma2(accB[1][1], x1, bA.y);
        fma2(accB[1][2], x1, bB.x); fma2(accB[1][3], x1, bB.y);
    }
    float biasA[8], biasB[8];
    *(float4*)&biasA[0] = *(const float4*)&ba[j0];
    *(float4*)&biasA[4] = *(const float4*)&ba[j0 + 4];
    *(float4*)&biasB[0] = *(const float4*)&bb[j0];
    *(float4*)&biasB[4] = *(const float4*)&bb[j0 + 4];
    #pragma unroll
    for (int rr = 0; rr < 2; rr++) {
        int r = r0 + rr;
        if (r < limit) {
            long off = (long)(node0 + r) * 64 + j0;
            float va[8], vb[8];
            #pragma unroll
            for (int q = 0; q < 4; q++) {
                float2 pa = unpack2(accA[rr][q]);
                float2 pb = unpack2(accB[rr][q]);
                va[2*q] = pa.x + biasA[2*q]; va[2*q+1] = pa.y + biasA[2*q+1];
                vb[2*q] = pb.x + biasB[2*q]; vb[2*q+1] = pb.y + biasB[2*q+1];
            }
            *(float4*)&g_MU[off]     = make_float4(va[0], va[1], va[2], va[3]);
            *(float4*)&g_MU[off + 4] = make_float4(va[4], va[5], va[6], va[7]);
            *(float4*)&outp[off]     = make_float4(vb[0], vb[1], vb[2], vb[3]);
            *(float4*)&outp[off + 4] = make_float4(vb[4], vb[5], vb[6], vb[7]);
        }
    }
}

// ---------------- decoder: 64 -> 32 -> 8 -> 1 + sumsq -------------------------
__global__ void decode_kernel(const float* __restrict__ dW1, const float* __restrict__ db1,
                              const float* __restrict__ dW2, const float* __restrict__ db2,
                              const float* __restrict__ dW3, const float* __restrict__ db3) {
    __shared__ float W1s[64 * 32];
    __shared__ float W2s[32 * 8];
    __shared__ float W3s[8];
    __shared__ float b1s[32], b2s[8], b3s;
    __shared__ float mus[4][64];
    __shared__ float v1s[4][32];
    __shared__ float v2s[4][8];
    __shared__ float dsq[4];
    int tid = threadIdx.x;  // 128
    for (int i = tid; i < 2048; i += 128) W1s[i] = dW1[i];
    for (int i = tid; i < 256;  i += 128) W2s[i] = dW2[i];
    if (tid < 8)  W3s[tid] = dW3[tid];
    if (tid < 32) b1s[tid] = db1[tid];
    if (tid >= 32 && tid < 40) b2s[tid - 32] = db2[tid - 32];
    if (tid == 40) b3s = db3[0];
    int w = tid >> 5, lane = tid & 31;
    int node = blockIdx.x * 4 + w;
    bool active = node < N_NODES;
    if (active) {
        mus[w][lane]      = g_MU[(long)node * 64 + lane];
        mus[w][lane + 32] = g_MU[(long)node * 64 + lane + 32];
    }
    __syncthreads();
    float d = 0.f;
    if (active) {
        float a1 = b1s[lane];
        #pragma unroll
        for (int k = 0; k < 64; k++) a1 += mus[w][k] * W1s[k * 32 + lane];
        v1s[w][lane] = leaky(a1);
        __syncwarp();
        if (lane < 8) {
            float a2 = b2s[lane];
            #pragma unroll
            for (int k = 0; k < 32; k++) a2 += v1s[w][k] * W2s[k * 8 + lane];
            v2s[w][lane] = leaky(a2);
        }
        __syncwarp();
        if (lane == 0) {
            d = b3s;
            #pragma unroll
            for (int o = 0; o < 8; o++) d += v2s[w][o] * W3s[o];
            g_dvec[node] = d;
        }
    }
    if (lane == 0) dsq[w] = active ? d * d : 0.f;
    __syncthreads();
    if (tid == 0) atomicAdd(&g_sumsq, dsq[0] + dsq[1] + dsq[2] + dsq[3]);
}

__global__ void norm_write_kernel(float* __restrict__ oz, float* __restrict__ om) {
    int i = blockIdx.x * blockDim.x + threadIdx.x;
    if (i >= N_NODES) return;
    float sc = 1.0f / fmaxf(sqrtf(g_sumsq), 1e-8f);
    float v = g_dvec[i] * sc;
    oz[i] = v;
    om[i] = v;
}

// ---------------- host launch ---------------------------------------------------
extern "C" void kernel_launch(void* const* d_in, const int* in_sizes, int n_in,
                              void* d_out, int out_size) {
    const float* x   = (const float*)d_in[0];
    const int*   hei = (const int*)d_in[1];   // int32 (JAX x64 disabled)
    const float *W1 = (const float*)d_in[2],  *b1  = (const float*)d_in[3];
    const float *g1 = (const float*)d_in[4],  *be1 = (const float*)d_in[5];
    const float *W2 = (const float*)d_in[6],  *b2  = (const float*)d_in[7];
    const float *Wmu= (const float*)d_in[8],  *bmu = (const float*)d_in[9];
    const float *Wlv= (const float*)d_in[10], *blv = (const float*)d_in[11];
    const float *dW1= (const float*)d_in[12], *db1 = (const float*)d_in[13];
    const float *dW2= (const float*)d_in[14], *db2 = (const float*)d_in[15];
    const float *dW3= (const float*)d_in[16], *db3 = (const float*)d_in[17];

    const int* nidx = hei;
    const int* eidx = hei + N_PINS;

    float* out    = (float*)d_out;
    float* out_z  = out;
    float* out_m  = out + N_NODES;
    float* out_lv = out + 2 * N_NODES;

    const int TB = 256;
    const int pins_blocks   = (N_PINS + TB - 1) / TB;      // 6250
    const int gather_blocks = (N_NODES * 32) / TB;         // 12500 (warp/row)
    const int mm_blocks     = (N_NODES + 63) / 64;         // 1563
    const int dec_blocks    = (N_NODES + 3) / 4;
    const int n_blocks      = (N_NODES + TB - 1) / TB;

    // CSR build
    zero_cnt_kernel<<<NB, TB>>>();
    hist_kernel<<<pins_blocks, TB>>>(nidx, eidx);
    scan1_kernel<<<NB, TB>>>();
    scan2_kernel<<<1, 512>>>();
    scan3_kernel<<<NB, TB>>>();
    fill_kernel<<<pins_blocks, TB>>>(nidx, eidx);

    // layer 1: gather(x) (32-wide) -> @W1+b1 -> LN -> leaky -> g_H
    gather_kernel<32, 0, 0><<<gather_blocks, TB>>>(x);
    gather_kernel<32, 1, 1><<<gather_blocks, TB>>>(nullptr);
    matmul2_kernel<32, 2, 0><<<mm_blocks, TB>>>(W1, b1, g1, be1, nullptr);

    // layer 2: gather(g_H) -> @W2+b2 -> leaky -> g_H
    gather_kernel<64, 0, 2><<<gather_blocks, TB>>>(nullptr);
    gather_kernel<64, 1, 1><<<gather_blocks, TB>>>(nullptr);
    matmul2_kernel<64, 1, 0><<<mm_blocks, TB>>>(W2, b2, nullptr, nullptr, nullptr);

    // mu / logvar share one gathered tensor; dual FFMA2 matmul
    gather_kernel<64, 0, 2><<<gather_blocks, TB>>>(nullptr);
    gather_kernel<64, 1, 1><<<gather_blocks, TB>>>(nullptr);
    matmul2_dual_kernel<<<mm_blocks, TB>>>(Wmu, bmu, Wlv, blv, out_lv);

    // decode(z = mu) once; z_orth == mu_orth in eval mode
    decode_kernel<<<dec_blocks, 128>>>(dW1, db1, dW2, db2, dW3, db3);
    norm_write_kernel<<<n_blocks, TB>>>(out_z, out_m);
}

// round 9
// speedup vs baseline: 1.1467x; 1.1000x over previous
#include <cuda_runtime.h>

#define N_NODES 100000
#define N_EDGES 100000
#define N_PINS  1600000
#define IN_DIM  32
#define HID     64
#define NEG     0.01f
#define NB      391           // ceil(100000/256)

__device__ __forceinline__ float leaky(float v) { return v >= 0.f ? v : NEG * v; }

// ---------------- scratch: __device__ globals ---------------------------------
__device__ __align__(16) float g_HE [N_EDGES * HID];   // edge-gather result
__device__ __align__(16) float g_H  [N_NODES * HID];   // hidden state
__device__ __align__(16) float g_MU [N_NODES * HID];   // mu
__device__ __align__(16) float g_dvec[N_NODES];
__device__ float g_sumsq;

// CSR
__device__ int g_ecnt [N_EDGES];
__device__ int g_ncnt [N_NODES];
__device__ int g_estart[N_EDGES + 1];
__device__ int g_nstart[N_NODES + 1];
__device__ int g_epins[N_PINS];   // node ids grouped by edge
__device__ int g_npins[N_PINS];   // edge ids grouped by node
__device__ int g_bsum_e[NB];
__device__ int g_bsum_n[NB];

// ---------------- CSR build ----------------------------------------------------
__global__ void zero_cnt_kernel() {
    int i = blockIdx.x * blockDim.x + threadIdx.x;
    if (i < N_EDGES) g_ecnt[i] = 0;
    if (i < N_NODES) g_ncnt[i] = 0;
    if (i == 0) g_sumsq = 0.f;
}

__global__ void hist_kernel(const int* __restrict__ nidx, const int* __restrict__ eidx) {
    int i = blockIdx.x * blockDim.x + threadIdx.x;
    if (i < N_PINS) {
        atomicAdd(&g_ncnt[nidx[i]], 1);
        atomicAdd(&g_ecnt[eidx[i]], 1);
    }
}

__global__ void scan1_kernel() {
    __shared__ int se[256], sn[256];
    int tid = threadIdx.x;
    int gid = blockIdx.x * 256 + tid;
    se[tid] = (gid < N_EDGES) ? g_ecnt[gid] : 0;
    sn[tid] = (gid < N_NODES) ? g_ncnt[gid] : 0;
    __syncthreads();
    for (int off = 128; off > 0; off >>= 1) {
        if (tid < off) { se[tid] += se[tid + off]; sn[tid] += sn[tid + off]; }
        __syncthreads();
    }
    if (tid == 0) { g_bsum_e[blockIdx.x] = se[0]; g_bsum_n[blockIdx.x] = sn[0]; }
}

__global__ void scan2_kernel() {
    __shared__ int se[512], sn[512];
    int tid = threadIdx.x;
    int ve = (tid < NB) ? g_bsum_e[tid] : 0;
    int vn = (tid < NB) ? g_bsum_n[tid] : 0;
    se[tid] = ve; sn[tid] = vn;
    __syncthreads();
    for (int off = 1; off < 512; off <<= 1) {
        int ae = (tid >= off) ? se[tid - off] : 0;
        int an = (tid >= off) ? sn[tid - off] : 0;
        __syncthreads();
        se[tid] += ae; sn[tid] += an;
        __syncthreads();
    }
    if (tid < NB) { g_bsum_e[tid] = se[tid] - ve; g_bsum_n[tid] = sn[tid] - vn; }
    if (tid == 0) { g_estart[N_EDGES] = N_PINS; g_nstart[N_NODES] = N_PINS; }
}

__global__ void scan3_kernel() {
    __shared__ int se[256], sn[256];
    int tid = threadIdx.x;
    int gid = blockIdx.x * 256 + tid;
    int ve = (gid < N_EDGES) ? g_ecnt[gid] : 0;
    int vn = (gid < N_NODES) ? g_ncnt[gid] : 0;
    se[tid] = ve; sn[tid] = vn;
    __syncthreads();
    for (int off = 1; off < 256; off <<= 1) {
        int ae = (tid >= off) ? se[tid - off] : 0;
        int an = (tid >= off) ? sn[tid - off] : 0;
        __syncthreads();
        se[tid] += ae; sn[tid] += an;
        __syncthreads();
    }
    if (gid < N_EDGES) { g_estart[gid] = g_bsum_e[blockIdx.x] + se[tid] - ve; g_ecnt[gid] = 0; }
    if (gid < N_NODES) { g_nstart[gid] = g_bsum_n[blockIdx.x] + sn[tid] - vn; g_ncnt[gid] = 0; }
}

__global__ void fill_kernel(const int* __restrict__ nidx, const int* __restrict__ eidx) {
    int i = blockIdx.x * blockDim.x + threadIdx.x;
    if (i >= N_PINS) return;
    int n = nidx[i], e = eidx[i];
    int pe = g_estart[e] + atomicAdd(&g_ecnt[e], 1);
    g_epins[pe] = n;
    int pn = g_nstart[n] + atomicAdd(&g_ncnt[n], 1);
    g_npins[pn] = e;
}

// ---------------- standalone edge-side gather (Round-6 form) ------------------
// g_HE[e] = (1/|e|) * sum_{n in e} src[n].  SRCSEL 0: param Xp (W=32). 2: g_H (W=64).
template <int W, int SRCSEL>
__global__ void gather_edge_kernel(const float* __restrict__ Xp) {
    constexpr int LPR = W / 4;
    constexpr int PPW = 32 / LPR;
    int row  = (blockIdx.x * blockDim.x + threadIdx.x) >> 5;
    int lane = threadIdx.x & 31;
    if (row >= N_EDGES) return;
    const float* src = (SRCSEL == 0) ? Xp : g_H;
    int sub = lane / LPR;
    int c4  = (lane % LPR) << 2;
    int s = g_estart[row], e = g_estart[row + 1];
    float ax = 0.f, ay = 0.f, az = 0.f, aw = 0.f;
    for (int i = s + sub; i < e; i += PPW) {
        int p = g_epins[i];
        float4 v = *(const float4*)(src + (long)p * W + c4);
        ax += v.x; ay += v.y; az += v.z; aw += v.w;
    }
    #pragma unroll
    for (int off = LPR; off < 32; off <<= 1) {
        ax += __shfl_xor_sync(0xffffffffu, ax, off);
        ay += __shfl_xor_sync(0xffffffffu, ay, off);
        az += __shfl_xor_sync(0xffffffffu, az, off);
        aw += __shfl_xor_sync(0xffffffffu, aw, off);
    }
    if (lane < LPR) {
        float inv = (e > s) ? 1.0f / (float)(e - s) : 0.0f;
        float4 r = make_float4(ax * inv, ay * inv, az * inv, aw * inv);
        *(float4*)(g_HE + (long)row * W + c4) = r;
    }
}

// ---------------- node-side gather into smem Xs (device inline) ---------------
// Each of 8 warps gathers 4 consecutive rows [node0 + wid*4 .. +3] from g_HE
// into Xs (padded row stride STRIDE). Scalar smem stores (padding breaks 16B).
template <int W, int STRIDE>
__device__ __forceinline__ void gather_rows_to_smem(float* Xs, int node0,
                                                    int wid, int lane) {
    constexpr int LPR = W / 4;
    constexpr int PPW = 32 / LPR;
    int sub = lane / LPR;
    int c4  = (lane % LPR) << 2;
    #pragma unroll
    for (int i = 0; i < 4; i++) {
        int lr  = wid * 4 + i;
        int row = node0 + lr;
        int s = g_nstart[row], e = g_nstart[row + 1];
        float ax = 0.f, ay = 0.f, az = 0.f, aw = 0.f;
        for (int t = s + sub; t < e; t += PPW) {
            int p = g_npins[t];
            float4 v = *(const float4*)(g_HE + (long)p * W + c4);
            ax += v.x; ay += v.y; az += v.z; aw += v.w;
        }
        #pragma unroll
        for (int off = LPR; off < 32; off <<= 1) {
            ax += __shfl_xor_sync(0xffffffffu, ax, off);
            ay += __shfl_xor_sync(0xffffffffu, ay, off);
            az += __shfl_xor_sync(0xffffffffu, az, off);
            aw += __shfl_xor_sync(0xffffffffu, aw, off);
        }
        if (lane < LPR) {
            float inv = (e > s) ? 1.0f / (float)(e - s) : 0.0f;
            float* p = Xs + lr * STRIDE + c4;
            p[0] = ax * inv; p[1] = ay * inv; p[2] = az * inv; p[3] = aw * inv;
        }
    }
}

// ---------------- fused: node-gather + matmul + LN + leaky -> g_H (layer 1) ---
__global__ __launch_bounds__(256) void fused_mm_ln_kernel(
    const float* __restrict__ Wm, const float* __restrict__ bias,
    const float* __restrict__ gg, const float* __restrict__ be) {
    __shared__ __align__(16) float Ws[32 * 64];
    __shared__ float Xs[32][33];
    int tid = threadIdx.x;
    int wid = tid >> 5, lane = tid & 31;
    for (int i = tid; i < 32 * 64; i += 256) Ws[i] = Wm[i];
    int node0 = blockIdx.x * 32;
    gather_rows_to_smem<32, 33>(&Xs[0][0], node0, wid, lane);
    __syncthreads();
    int j0 = (tid & 15) << 2;
    int r0 = (tid >> 4) << 1;
    float acc[2][4] = {};
    #pragma unroll
    for (int k = 0; k < 32; k++) {
        float x0 = Xs[r0][k], x1 = Xs[r0 + 1][k];
        float4 w = *(const float4*)&Ws[k * 64 + j0];
        acc[0][0] += x0 * w.x; acc[0][1] += x0 * w.y; acc[0][2] += x0 * w.z; acc[0][3] += x0 * w.w;
        acc[1][0] += x1 * w.x; acc[1][1] += x1 * w.y; acc[1][2] += x1 * w.z; acc[1][3] += x1 * w.w;
    }
    float b0 = bias[j0], b1 = bias[j0+1], b2 = bias[j0+2], b3 = bias[j0+3];
    float g0 = gg[j0], gg1 = gg[j0+1], g2 = gg[j0+2], g3 = gg[j0+3];
    float e0 = be[j0], e1 = be[j0+1], e2 = be[j0+2], e3 = be[j0+3];
    #pragma unroll
    for (int rr = 0; rr < 2; rr++) {
        float vx = acc[rr][0] + b0, vy = acc[rr][1] + b1;
        float vz = acc[rr][2] + b2, vw = acc[rr][3] + b3;
        float s  = vx + vy + vz + vw;
        float sq = vx*vx + vy*vy + vz*vz + vw*vw;
        #pragma unroll
        for (int off = 1; off < 16; off <<= 1) {
            s  += __shfl_xor_sync(0xffffffffu, s,  off);
            sq += __shfl_xor_sync(0xffffffffu, sq, off);
        }
        float mean = s * (1.0f / 64.0f);
        float var  = sq * (1.0f / 64.0f) - mean * mean;
        float rstd = rsqrtf(var + 1e-5f);
        float4 o;
        o.x = leaky((vx - mean) * rstd * g0 + e0);
        o.y = leaky((vy - mean) * rstd * gg1 + e1);
        o.z = leaky((vz - mean) * rstd * g2 + e2);
        o.w = leaky((vw - mean) * rstd * g3 + e3);
        *(float4*)&g_H[(long)(node0 + r0 + rr) * 64 + j0] = o;
    }
}

// ---------------- fused: node-gather + matmul + leaky -> g_H (layer 2) --------
__global__ __launch_bounds__(256) void fused_mm_leaky_kernel(
    const float* __restrict__ Wm, const float* __restrict__ bias) {
    __shared__ __align__(16) float Ws[64 * 64];
    __shared__ float Xs[32][65];
    int tid = threadIdx.x;
    int wid = tid >> 5, lane = tid & 31;
    for (int i = tid; i < 64 * 64; i += 256) Ws[i] = Wm[i];
    int node0 = blockIdx.x * 32;
    gather_rows_to_smem<64, 65>(&Xs[0][0], node0, wid, lane);
    __syncthreads();
    int j0 = (tid & 15) << 2;
    int r0 = (tid >> 4) << 1;
    float acc[2][4] = {};
    #pragma unroll
    for (int k = 0; k < 64; k++) {
        float x0 = Xs[r0][k], x1 = Xs[r0 + 1][k];
        float4 w = *(const float4*)&Ws[k * 64 + j0];
        acc[0][0] += x0 * w.x; acc[0][1] += x0 * w.y; acc[0][2] += x0 * w.z; acc[0][3] += x0 * w.w;
        acc[1][0] += x1 * w.x; acc[1][1] += x1 * w.y; acc[1][2] += x1 * w.z; acc[1][3] += x1 * w.w;
    }
    float b0 = bias[j0], b1 = bias[j0+1], b2 = bias[j0+2], b3 = bias[j0+3];
    #pragma unroll
    for (int rr = 0; rr < 2; rr++) {
        float4 v;
        v.x = leaky(acc[rr][0] + b0); v.y = leaky(acc[rr][1] + b1);
        v.z = leaky(acc[rr][2] + b2); v.w = leaky(acc[rr][3] + b3);
        *(float4*)&g_H[(long)(node0 + r0 + rr) * 64 + j0] = v;
    }
}

// ---------------- fused: node-gather + dual matmul -> g_MU, outp (layer 3) ----
__global__ __launch_bounds__(256) void fused_mm_dual_kernel(
    const float* __restrict__ Wa, const float* __restrict__ ba,
    const float* __restrict__ Wb, const float* __restrict__ bb,
    float* __restrict__ outp) {
    __shared__ __align__(16) float Wsa[64 * 64];
    __shared__ __align__(16) float Wsb[64 * 64];
    __shared__ float Xs[32][65];
    int tid = threadIdx.x;
    int wid = tid >> 5, lane = tid & 31;
    for (int i = tid; i < 64 * 64; i += 256) { Wsa[i] = Wa[i]; Wsb[i] = Wb[i]; }
    int node0 = blockIdx.x * 32;
    gather_rows_to_smem<64, 65>(&Xs[0][0], node0, wid, lane);
    __syncthreads();
    int j0 = (tid & 15) << 2;
    int r0 = (tid >> 4) << 1;
    float accA[2][4] = {}, accB[2][4] = {};
    #pragma unroll
    for (int k = 0; k < 64; k++) {
        float x0 = Xs[r0][k], x1 = Xs[r0 + 1][k];
        float4 wa = *(const float4*)&Wsa[k * 64 + j0];
        float4 wb = *(const float4*)&Wsb[k * 64 + j0];
        accA[0][0] += x0*wa.x; accA[0][1] += x0*wa.y; accA[0][2] += x0*wa.z; accA[0][3] += x0*wa.w;
        accA[1][0] += x1*wa.x; accA[1][1] += x1*wa.y; accA[1][2] += x1*wa.z; accA[1][3] += x1*wa.w;
        accB[0][0] += x0*wb.x; accB[0][1] += x0*wb.y; accB[0][2] += x0*wb.z; accB[0][3] += x0*wb.w;
        accB[1][0] += x1*wb.x; accB[1][1] += x1*wb.y; accB[1][2] += x1*wb.z; accB[1][3] += x1*wb.w;
    }
    float a0 = ba[j0], a1 = ba[j0+1], a2 = ba[j0+2], a3 = ba[j0+3];
    float c0 = bb[j0], c1 = bb[j0+1], c2 = bb[j0+2], c3 = bb[j0+3];
    #pragma unroll
    for (int rr = 0; rr < 2; rr++) {
        long rowoff = (long)(node0 + r0 + rr) * 64 + j0;
        float4 va = make_float4(accA[rr][0]+a0, accA[rr][1]+a1, accA[rr][2]+a2, accA[rr][3]+a3);
        float4 vb = make_float4(accB[rr][0]+c0, accB[rr][1]+c1, accB[rr][2]+c2, accB[rr][3]+c3);
        *(float4*)&g_MU[rowoff] = va;
        *(float4*)&outp[rowoff] = vb;
    }
}

// ---------------- decoder: 64 -> 32 -> 8 -> 1 + sumsq -------------------------
__global__ void decode_kernel(const float* __restrict__ dW1, const float* __restrict__ db1,
                              const float* __restrict__ dW2, const float* __restrict__ db2,
                              const float* __restrict__ dW3, const float* __restrict__ db3) {
    __shared__ float W1s[64 * 32];
    __shared__ float W2s[32 * 8];
    __shared__ float W3s[8];
    __shared__ float b1s[32], b2s[8], b3s;
    __shared__ float mus[4][64];
    __shared__ float v1s[4][32];
    __shared__ float v2s[4][8];
    __shared__ float dsq[4];
    int tid = threadIdx.x;  // 128
    for (int i = tid; i < 2048; i += 128) W1s[i] = dW1[i];
    for (int i = tid; i < 256;  i += 128) W2s[i] = dW2[i];
    if (tid < 8)  W3s[tid] = dW3[tid];
    if (tid < 32) b1s[tid] = db1[tid];
    if (tid >= 32 && tid < 40) b2s[tid - 32] = db2[tid - 32];
    if (tid == 40) b3s = db3[0];
    int w = tid >> 5, lane = tid & 31;
    int node = blockIdx.x * 4 + w;
    bool active = node < N_NODES;
    if (active) {
        mus[w][lane]      = g_MU[(long)node * 64 + lane];
        mus[w][lane + 32] = g_MU[(long)node * 64 + lane + 32];
    }
    __syncthreads();
    float d = 0.f;
    if (active) {
        float a1 = b1s[lane];
        #pragma unroll
        for (int k = 0; k < 64; k++) a1 += mus[w][k] * W1s[k * 32 + lane];
        v1s[w][lane] = leaky(a1);
        __syncwarp();
        if (lane < 8) {
            float a2 = b2s[lane];
            #pragma unroll
            for (int k = 0; k < 32; k++) a2 += v1s[w][k] * W2s[k * 8 + lane];
            v2s[w][lane] = leaky(a2);
        }
        __syncwarp();
        if (lane == 0) {
            d = b3s;
            #pragma unroll
            for (int o = 0; o < 8; o++) d += v2s[w][o] * W3s[o];
            g_dvec[node] = d;
        }
    }
    if (lane == 0) dsq[w] = active ? d * d : 0.f;
    __syncthreads();
    if (tid == 0) atomicAdd(&g_sumsq, dsq[0] + dsq[1] + dsq[2] + dsq[3]);
}

__global__ void norm_write_kernel(float* __restrict__ oz, float* __restrict__ om) {
    int i = blockIdx.x * blockDim.x + threadIdx.x;
    if (i >= N_NODES) return;
    float sc = 1.0f / fmaxf(sqrtf(g_sumsq), 1e-8f);
    float v = g_dvec[i] * sc;
    oz[i] = v;
    om[i] = v;
}

// ---------------- host launch ---------------------------------------------------
extern "C" void kernel_launch(void* const* d_in, const int* in_sizes, int n_in,
                              void* d_out, int out_size) {
    const float* x   = (const float*)d_in[0];
    const int*   hei = (const int*)d_in[1];   // int32 (JAX x64 disabled)
    const float *W1 = (const float*)d_in[2],  *b1  = (const float*)d_in[3];
    const float *g1 = (const float*)d_in[4],  *be1 = (const float*)d_in[5];
    const float *W2 = (const float*)d_in[6],  *b2  = (const float*)d_in[7];
    const float *Wmu= (const float*)d_in[8],  *bmu = (const float*)d_in[9];
    const float *Wlv= (const float*)d_in[10], *blv = (const float*)d_in[11];
    const float *dW1= (const float*)d_in[12], *db1 = (const float*)d_in[13];
    const float *dW2= (const float*)d_in[14], *db2 = (const float*)d_in[15];
    const float *dW3= (const float*)d_in[16], *db3 = (const float*)d_in[17];

    const int* nidx = hei;
    const int* eidx = hei + N_PINS;

    float* out    = (float*)d_out;
    float* out_z  = out;
    float* out_m  = out + N_NODES;
    float* out_lv = out + 2 * N_NODES;

    const int TB = 256;
    const int pins_blocks   = (N_PINS + TB - 1) / TB;      // 6250
    const int gather_blocks = (N_EDGES * 32) / TB;         // 12500 (warp/row)
    const int mm_blocks     = N_NODES / 32;                // 3125
    const int dec_blocks    = (N_NODES + 3) / 4;
    const int n_blocks      = (N_NODES + TB - 1) / TB;

    // CSR build
    zero_cnt_kernel<<<NB, TB>>>();
    hist_kernel<<<pins_blocks, TB>>>(nidx, eidx);
    scan1_kernel<<<NB, TB>>>();
    scan2_kernel<<<1, 512>>>();
    scan3_kernel<<<NB, TB>>>();
    fill_kernel<<<pins_blocks, TB>>>(nidx, eidx);

    // layer 1: edge-gather(x) (32-wide) -> fused node-gather+@W1+LN+leaky -> g_H
    gather_edge_kernel<32, 0><<<gather_blocks, TB>>>(x);
    fused_mm_ln_kernel<<<mm_blocks, TB>>>(W1, b1, g1, be1);

    // layer 2: edge-gather(g_H) -> fused node-gather+@W2+leaky -> g_H
    gather_edge_kernel<64, 2><<<gather_blocks, TB>>>(nullptr);
    fused_mm_leaky_kernel<<<mm_blocks, TB>>>(W2, b2);

    // layer 3: edge-gather(g_H) -> fused node-gather + dual matmul -> g_MU, out_lv
    gather_edge_kernel<64, 2><<<gather_blocks, TB>>>(nullptr);
    fused_mm_dual_kernel<<<mm_blocks, TB>>>(Wmu, bmu, Wlv, blv, out_lv);

    // decode(z = mu) once; z_orth == mu_orth in eval mode
    decode_kernel<<<dec_blocks, 128>>>(dW1, db1, dW2, db2, dW3, db3);
    norm_write_kernel<<<n_blocks, TB>>>(out_z, out_m);
}

// round 10
// speedup vs baseline: 1.2402x; 1.0815x over previous
#include <cuda_runtime.h>
#include <cuda_fp16.h>

#define N_NODES 100000
#define N_EDGES 100000
#define N_PINS  1600000
#define IN_DIM  32
#define HID     64
#define NEG     0.01f
#define NB      391           // ceil(100000/256)

__device__ __forceinline__ float leaky(float v) { return v >= 0.f ? v : NEG * v; }
__device__ __forceinline__ unsigned h2u(__half2 h) { return *reinterpret_cast<unsigned*>(&h); }
__device__ __forceinline__ __half2 u2h(unsigned u) { return *reinterpret_cast<__half2*>(&u); }

// ---------------- scratch: __device__ globals ---------------------------------
__device__ __align__(16) __half g_HE [N_EDGES * HID];  // edge-gather result (fp16)
__device__ __align__(16) __half g_H  [N_NODES * HID];  // hidden state (fp16)
__device__ __align__(16) float  g_MU [N_NODES * HID];  // mu (fp32)
__device__ __align__(16) float  g_dvec[N_NODES];
__device__ float g_sumsq;

// CSR
__device__ int g_ecnt [N_EDGES];
__device__ int g_ncnt [N_NODES];
__device__ int g_estart[N_EDGES + 1];
__device__ int g_nstart[N_NODES + 1];
__device__ int g_epins[N_PINS];   // node ids grouped by edge
__device__ int g_npins[N_PINS];   // edge ids grouped by node
__device__ int g_bsum_e[NB];
__device__ int g_bsum_n[NB];

// ---------------- CSR build ----------------------------------------------------
__global__ void zero_cnt_kernel() {
    int i = blockIdx.x * blockDim.x + threadIdx.x;
    if (i < N_EDGES) g_ecnt[i] = 0;
    if (i < N_NODES) g_ncnt[i] = 0;
    if (i == 0) g_sumsq = 0.f;
}

__global__ void hist_kernel(const int* __restrict__ nidx, const int* __restrict__ eidx) {
    int i = blockIdx.x * blockDim.x + threadIdx.x;
    if (i < N_PINS) {
        atomicAdd(&g_ncnt[nidx[i]], 1);
        atomicAdd(&g_ecnt[eidx[i]], 1);
    }
}

__global__ void scan1_kernel() {
    __shared__ int se[256], sn[256];
    int tid = threadIdx.x;
    int gid = blockIdx.x * 256 + tid;
    se[tid] = (gid < N_EDGES) ? g_ecnt[gid] : 0;
    sn[tid] = (gid < N_NODES) ? g_ncnt[gid] : 0;
    __syncthreads();
    for (int off = 128; off > 0; off >>= 1) {
        if (tid < off) { se[tid] += se[tid + off]; sn[tid] += sn[tid + off]; }
        __syncthreads();
    }
    if (tid == 0) { g_bsum_e[blockIdx.x] = se[0]; g_bsum_n[blockIdx.x] = sn[0]; }
}

__global__ void scan2_kernel() {
    __shared__ int se[512], sn[512];
    int tid = threadIdx.x;
    int ve = (tid < NB) ? g_bsum_e[tid] : 0;
    int vn = (tid < NB) ? g_bsum_n[tid] : 0;
    se[tid] = ve; sn[tid] = vn;
    __syncthreads();
    for (int off = 1; off < 512; off <<= 1) {
        int ae = (tid >= off) ? se[tid - off] : 0;
        int an = (tid >= off) ? sn[tid - off] : 0;
        __syncthreads();
        se[tid] += ae; sn[tid] += an;
        __syncthreads();
    }
    if (tid < NB) { g_bsum_e[tid] = se[tid] - ve; g_bsum_n[tid] = sn[tid] - vn; }
    if (tid == 0) { g_estart[N_EDGES] = N_PINS; g_nstart[N_NODES] = N_PINS; }
}

__global__ void scan3_kernel() {
    __shared__ int se[256], sn[256];
    int tid = threadIdx.x;
    int gid = blockIdx.x * 256 + tid;
    int ve = (gid < N_EDGES) ? g_ecnt[gid] : 0;
    int vn = (gid < N_NODES) ? g_ncnt[gid] : 0;
    se[tid] = ve; sn[tid] = vn;
    __syncthreads();
    for (int off = 1; off < 256; off <<= 1) {
        int ae = (tid >= off) ? se[tid - off] : 0;
        int an = (tid >= off) ? sn[tid - off] : 0;
        __syncthreads();
        se[tid] += ae; sn[tid] += an;
        __syncthreads();
    }
    if (gid < N_EDGES) { g_estart[gid] = g_bsum_e[blockIdx.x] + se[tid] - ve; g_ecnt[gid] = 0; }
    if (gid < N_NODES) { g_nstart[gid] = g_bsum_n[blockIdx.x] + sn[tid] - vn; g_ncnt[gid] = 0; }
}

__global__ void fill_kernel(const int* __restrict__ nidx, const int* __restrict__ eidx) {
    int i = blockIdx.x * blockDim.x + threadIdx.x;
    if (i >= N_PINS) return;
    int n = nidx[i], e = eidx[i];
    int pe = g_estart[e] + atomicAdd(&g_ecnt[e], 1);
    g_epins[pe] = n;
    int pn = g_nstart[n] + atomicAdd(&g_ncnt[n], 1);
    g_npins[pn] = e;
}

// ---------------- edge gather, layer 1: x(fp32,32) -> g_HE(fp16,32) -----------
// Warp/row; lane owns 4 fp32 cols (16B load); 4 pins in flight.
__global__ void gather_edge_x_kernel(const float* __restrict__ Xp) {
    int row  = (blockIdx.x * blockDim.x + threadIdx.x) >> 5;
    int lane = threadIdx.x & 31;
    if (row >= N_EDGES) return;
    int sub = lane >> 3;           // PPW = 4
    int c4  = (lane & 7) << 2;
    int s = g_estart[row], e = g_estart[row + 1];
    float ax = 0.f, ay = 0.f, az = 0.f, aw = 0.f;
    for (int i = s + sub; i < e; i += 4) {
        int p = g_epins[i];
        float4 v = *(const float4*)(Xp + (long)p * 32 + c4);
        ax += v.x; ay += v.y; az += v.z; aw += v.w;
    }
    #pragma unroll
    for (int off = 8; off < 32; off <<= 1) {
        ax += __shfl_xor_sync(0xffffffffu, ax, off);
        ay += __shfl_xor_sync(0xffffffffu, ay, off);
        az += __shfl_xor_sync(0xffffffffu, az, off);
        aw += __shfl_xor_sync(0xffffffffu, aw, off);
    }
    if (lane < 8) {
        float inv = (e > s) ? 1.0f / (float)(e - s) : 0.0f;
        uint2 u;
        u.x = h2u(__floats2half2_rn(ax * inv, ay * inv));
        u.y = h2u(__floats2half2_rn(az * inv, aw * inv));
        *(uint2*)(g_HE + (long)row * 32 + c4) = u;
    }
}

// ---------------- edge gather, layers 2/3: g_H(fp16,64) -> g_HE(fp16,64) ------
// Lane owns 8 fp16 cols (16B load); 4 pins in flight.
__global__ void gather_edge_h_kernel() {
    int row  = (blockIdx.x * blockDim.x + threadIdx.x) >> 5;
    int lane = threadIdx.x & 31;
    if (row >= N_EDGES) return;
    int sub = lane >> 3;           // PPW = 4
    int c8  = (lane & 7) << 3;
    int s = g_estart[row], e = g_estart[row + 1];
    float a[8] = {};
    for (int i = s + sub; i < e; i += 4) {
        int p = g_epins[i];
        uint4 v = *(const uint4*)(g_H + (long)p * 64 + c8);
        float2 f0 = __half22float2(u2h(v.x));
        float2 f1 = __half22float2(u2h(v.y));
        float2 f2 = __half22float2(u2h(v.z));
        float2 f3 = __half22float2(u2h(v.w));
        a[0] += f0.x; a[1] += f0.y; a[2] += f1.x; a[3] += f1.y;
        a[4] += f2.x; a[5] += f2.y; a[6] += f3.x; a[7] += f3.y;
    }
    #pragma unroll
    for (int off = 8; off < 32; off <<= 1)
        #pragma unroll
        for (int q = 0; q < 8; q++)
            a[q] += __shfl_xor_sync(0xffffffffu, a[q], off);
    if (lane < 8) {
        float inv = (e > s) ? 1.0f / (float)(e - s) : 0.0f;
        uint4 u;
        u.x = h2u(__floats2half2_rn(a[0] * inv, a[1] * inv));
        u.y = h2u(__floats2half2_rn(a[2] * inv, a[3] * inv));
        u.z = h2u(__floats2half2_rn(a[4] * inv, a[5] * inv));
        u.w = h2u(__floats2half2_rn(a[6] * inv, a[7] * inv));
        *(uint4*)(g_HE + (long)row * 64 + c8) = u;
    }
}

// ---------------- node gather into smem Xs (fp16 src, fp32 accum) -------------
// Each of 8 warps gathers 4 rows. W: fp16 row width (32 or 64). STRIDE: Xs pitch.
template <int W, int STRIDE>
__device__ __forceinline__ void gather_rows_to_smem(float* Xs, int node0,
                                                    int wid, int lane) {
    int sub = lane >> 3;           // PPW = 4
    #pragma unroll
    for (int i = 0; i < 4; i++) {
        int lr  = wid * 4 + i;
        int row = node0 + lr;
        int s = g_nstart[row], e = g_nstart[row + 1];
        if (W == 32) {
            int c4 = (lane & 7) << 2;   // 4 halfs (8B) per lane
            float ax = 0.f, ay = 0.f, az = 0.f, aw = 0.f;
            for (int t = s + sub; t < e; t += 4) {
                int p = g_npins[t];
                uint2 v = *(const uint2*)(g_HE + (long)p * 32 + c4);
                float2 f0 = __half22float2(u2h(v.x));
                float2 f1 = __half22float2(u2h(v.y));
                ax += f0.x; ay += f0.y; az += f1.x; aw += f1.y;
            }
            #pragma unroll
            for (int off = 8; off < 32; off <<= 1) {
                ax += __shfl_xor_sync(0xffffffffu, ax, off);
                ay += __shfl_xor_sync(0xffffffffu, ay, off);
                az += __shfl_xor_sync(0xffffffffu, az, off);
                aw += __shfl_xor_sync(0xffffffffu, aw, off);
            }
            if (lane < 8) {
                float inv = (e > s) ? 1.0f / (float)(e - s) : 0.0f;
                float* p = Xs + lr * STRIDE + c4;
                p[0] = ax * inv; p[1] = ay * inv; p[2] = az * inv; p[3] = aw * inv;
            }
        } else {
            int c8 = (lane & 7) << 3;   // 8 halfs (16B) per lane
            float a[8] = {};
            for (int t = s + sub; t < e; t += 4) {
                int p = g_npins[t];
                uint4 v = *(const uint4*)(g_HE + (long)p * 64 + c8);
                float2 f0 = __half22float2(u2h(v.x));
                float2 f1 = __half22float2(u2h(v.y));
                float2 f2 = __half22float2(u2h(v.z));
                float2 f3 = __half22float2(u2h(v.w));
                a[0] += f0.x; a[1] += f0.y; a[2] += f1.x; a[3] += f1.y;
                a[4] += f2.x; a[5] += f2.y; a[6] += f3.x; a[7] += f3.y;
            }
            #pragma unroll
            for (int off = 8; off < 32; off <<= 1)
                #pragma unroll
                for (int q = 0; q < 8; q++)
                    a[q] += __shfl_xor_sync(0xffffffffu, a[q], off);
            if (lane < 8) {
                float inv = (e > s) ? 1.0f / (float)(e - s) : 0.0f;
                float* p = Xs + lr * STRIDE + c8;
                #pragma unroll
                for (int q = 0; q < 8; q++) p[q] = a[q] * inv;
            }
        }
    }
}

// ---------------- fused: node-gather + matmul + LN + leaky -> g_H (layer 1) ---
__global__ __launch_bounds__(256) void fused_mm_ln_kernel(
    const float* __restrict__ Wm, const float* __restrict__ bias,
    const float* __restrict__ gg, const float* __restrict__ be) {
    __shared__ __align__(16) float Ws[32 * 64];
    __shared__ float Xs[32][33];
    int tid = threadIdx.x;
    int wid = tid >> 5, lane = tid & 31;
    for (int i = tid; i < 32 * 64; i += 256) Ws[i] = Wm[i];
    int node0 = blockIdx.x * 32;
    gather_rows_to_smem<32, 33>(&Xs[0][0], node0, wid, lane);
    __syncthreads();
    int j0 = (tid & 15) << 2;
    int r0 = (tid >> 4) << 1;
    float acc[2][4] = {};
    #pragma unroll
    for (int k = 0; k < 32; k++) {
        float x0 = Xs[r0][k], x1 = Xs[r0 + 1][k];
        float4 w = *(const float4*)&Ws[k * 64 + j0];
        acc[0][0] += x0 * w.x; acc[0][1] += x0 * w.y; acc[0][2] += x0 * w.z; acc[0][3] += x0 * w.w;
        acc[1][0] += x1 * w.x; acc[1][1] += x1 * w.y; acc[1][2] += x1 * w.z; acc[1][3] += x1 * w.w;
    }
    float b0 = bias[j0], b1 = bias[j0+1], b2 = bias[j0+2], b3 = bias[j0+3];
    float g0 = gg[j0], gg1 = gg[j0+1], g2 = gg[j0+2], g3 = gg[j0+3];
    float e0 = be[j0], e1 = be[j0+1], e2 = be[j0+2], e3 = be[j0+3];
    #pragma unroll
    for (int rr = 0; rr < 2; rr++) {
        float vx = acc[rr][0] + b0, vy = acc[rr][1] + b1;
        float vz = acc[rr][2] + b2, vw = acc[rr][3] + b3;
        float s  = vx + vy + vz + vw;
        float sq = vx*vx + vy*vy + vz*vz + vw*vw;
        #pragma unroll
        for (int off = 1; off < 16; off <<= 1) {
            s  += __shfl_xor_sync(0xffffffffu, s,  off);
            sq += __shfl_xor_sync(0xffffffffu, sq, off);
        }
        float mean = s * (1.0f / 64.0f);
        float var  = sq * (1.0f / 64.0f) - mean * mean;
        float rstd = rsqrtf(var + 1e-5f);
        float ox = leaky((vx - mean) * rstd * g0 + e0);
        float oy = leaky((vy - mean) * rstd * gg1 + e1);
        float oz = leaky((vz - mean) * rstd * g2 + e2);
        float ow = leaky((vw - mean) * rstd * g3 + e3);
        uint2 u;
        u.x = h2u(__floats2half2_rn(ox, oy));
        u.y = h2u(__floats2half2_rn(oz, ow));
        *(uint2*)(g_H + (long)(node0 + r0 + rr) * 64 + j0) = u;
    }
}

// ---------------- fused: node-gather + matmul + leaky -> g_H (layer 2) --------
__global__ __launch_bounds__(256) void fused_mm_leaky_kernel(
    const float* __restrict__ Wm, const float* __restrict__ bias) {
    __shared__ __align__(16) float Ws[64 * 64];
    __shared__ float Xs[32][65];
    int tid = threadIdx.x;
    int wid = tid >> 5, lane = tid & 31;
    for (int i = tid; i < 64 * 64; i += 256) Ws[i] = Wm[i];
    int node0 = blockIdx.x * 32;
    gather_rows_to_smem<64, 65>(&Xs[0][0], node0, wid, lane);
    __syncthreads();
    int j0 = (tid & 15) << 2;
    int r0 = (tid >> 4) << 1;
    float acc[2][4] = {};
    #pragma unroll
    for (int k = 0; k < 64; k++) {
        float x0 = Xs[r0][k], x1 = Xs[r0 + 1][k];
        float4 w = *(const float4*)&Ws[k * 64 + j0];
        acc[0][0] += x0 * w.x; acc[0][1] += x0 * w.y; acc[0][2] += x0 * w.z; acc[0][3] += x0 * w.w;
        acc[1][0] += x1 * w.x; acc[1][1] += x1 * w.y; acc[1][2] += x1 * w.z; acc[1][3] += x1 * w.w;
    }
    float b0 = bias[j0], b1 = bias[j0+1], b2 = bias[j0+2], b3 = bias[j0+3];
    #pragma unroll
    for (int rr = 0; rr < 2; rr++) {
        float ox = leaky(acc[rr][0] + b0);
        float oy = leaky(acc[rr][1] + b1);
        float oz = leaky(acc[rr][2] + b2);
        float ow = leaky(acc[rr][3] + b3);
        uint2 u;
        u.x = h2u(__floats2half2_rn(ox, oy));
        u.y = h2u(__floats2half2_rn(oz, ow));
        *(uint2*)(g_H + (long)(node0 + r0 + rr) * 64 + j0) = u;
    }
}

// ---------------- fused: node-gather + dual matmul -> g_MU, outp (layer 3) ----
__global__ __launch_bounds__(256) void fused_mm_dual_kernel(
    const float* __restrict__ Wa, const float* __restrict__ ba,
    const float* __restrict__ Wb, const float* __restrict__ bb,
    float* __restrict__ outp) {
    __shared__ __align__(16) float Wsa[64 * 64];
    __shared__ __align__(16) float Wsb[64 * 64];
    __shared__ float Xs[32][65];
    int tid = threadIdx.x;
    int wid = tid >> 5, lane = tid & 31;
    for (int i = tid; i < 64 * 64; i += 256) { Wsa[i] = Wa[i]; Wsb[i] = Wb[i]; }
    int node0 = blockIdx.x * 32;
    gather_rows_to_smem<64, 65>(&Xs[0][0], node0, wid, lane);
    __syncthreads();
    int j0 = (tid & 15) << 2;
    int r0 = (tid >> 4) << 1;
    float accA[2][4] = {}, accB[2][4] = {};
    #pragma unroll
    for (int k = 0; k < 64; k++) {
        float x0 = Xs[r0][k], x1 = Xs[r0 + 1][k];
        float4 wa = *(const float4*)&Wsa[k * 64 + j0];
        float4 wb = *(const float4*)&Wsb[k * 64 + j0];
        accA[0][0] += x0*wa.x; accA[0][1] += x0*wa.y; accA[0][2] += x0*wa.z; accA[0][3] += x0*wa.w;
        accA[1][0] += x1*wa.x; accA[1][1] += x1*wa.y; accA[1][2] += x1*wa.z; accA[1][3] += x1*wa.w;
        accB[0][0] += x0*wb.x; accB[0][1] += x0*wb.y; accB[0][2] += x0*wb.z; accB[0][3] += x0*wb.w;
        accB[1][0] += x1*wb.x; accB[1][1] += x1*wb.y; accB[1][2] += x1*wb.z; accB[1][3] += x1*wb.w;
    }
    float a0 = ba[j0], a1 = ba[j0+1], a2 = ba[j0+2], a3 = ba[j0+3];
    float c0 = bb[j0], c1 = bb[j0+1], c2 = bb[j0+2], c3 = bb[j0+3];
    #pragma unroll
    for (int rr = 0; rr < 2; rr++) {
        long rowoff = (long)(node0 + r0 + rr) * 64 + j0;
        float4 va = make_float4(accA[rr][0]+a0, accA[rr][1]+a1, accA[rr][2]+a2, accA[rr][3]+a3);
        float4 vb = make_float4(accB[rr][0]+c0, accB[rr][1]+c1, accB[rr][2]+c2, accB[rr][3]+c3);
        *(float4*)&g_MU[rowoff] = va;
        *(float4*)&outp[rowoff] = vb;
    }
}

// ---------------- decoder: 64 -> 32 -> 8 -> 1 + sumsq -------------------------
__global__ void decode_kernel(const float* __restrict__ dW1, const float* __restrict__ db1,
                              const float* __restrict__ dW2, const float* __restrict__ db2,
                              const float* __restrict__ dW3, const float* __restrict__ db3) {
    __shared__ float W1s[64 * 32];
    __shared__ float W2s[32 * 8];
    __shared__ float W3s[8];
    __shared__ float b1s[32], b2s[8], b3s;
    __shared__ float mus[4][64];
    __shared__ float v1s[4][32];
    __shared__ float v2s[4][8];
    __shared__ float dsq[4];
    int tid = threadIdx.x;  // 128
    for (int i = tid; i < 2048; i += 128) W1s[i] = dW1[i];
    for (int i = tid; i < 256;  i += 128) W2s[i] = dW2[i];
    if (tid < 8)  W3s[tid] = dW3[tid];
    if (tid < 32) b1s[tid] = db1[tid];
    if (tid >= 32 && tid < 40) b2s[tid - 32] = db2[tid - 32];
    if (tid == 40) b3s = db3[0];
    int w = tid >> 5, lane = tid & 31;
    int node = blockIdx.x * 4 + w;
    bool active = node < N_NODES;
    if (active) {
        mus[w][lane]      = g_MU[(long)node * 64 + lane];
        mus[w][lane + 32] = g_MU[(long)node * 64 + lane + 32];
    }
    __syncthreads();
    float d = 0.f;
    if (active) {
        float a1 = b1s[lane];
        #pragma unroll
        for (int k = 0; k < 64; k++) a1 += mus[w][k] * W1s[k * 32 + lane];
        v1s[w][lane] = leaky(a1);
        __syncwarp();
        if (lane < 8) {
            float a2 = b2s[lane];
            #pragma unroll
            for (int k = 0; k < 32; k++) a2 += v1s[w][k] * W2s[k * 8 + lane];
            v2s[w][lane] = leaky(a2);
        }
        __syncwarp();
        if (lane == 0) {
            d = b3s;
            #pragma unroll
            for (int o = 0; o < 8; o++) d += v2s[w][o] * W3s[o];
            g_dvec[node] = d;
        }
    }
    if (lane == 0) dsq[w] = active ? d * d : 0.f;
    __syncthreads();
    if (tid == 0) atomicAdd(&g_sumsq, dsq[0] + dsq[1] + dsq[2] + dsq[3]);
}

__global__ void norm_write_kernel(float* __restrict__ oz, float* __restrict__ om) {
    int i = blockIdx.x * blockDim.x + threadIdx.x;
    if (i >= N_NODES) return;
    float sc = 1.0f / fmaxf(sqrtf(g_sumsq), 1e-8f);
    float v = g_dvec[i] * sc;
    oz[i] = v;
    om[i] = v;
}

// ---------------- host launch ---------------------------------------------------
extern "C" void kernel_launch(void* const* d_in, const int* in_sizes, int n_in,
                              void* d_out, int out_size) {
    const float* x   = (const float*)d_in[0];
    const int*   hei = (const int*)d_in[1];   // int32 (JAX x64 disabled)
    const float *W1 = (const float*)d_in[2],  *b1  = (const float*)d_in[3];
    const float *g1 = (const float*)d_in[4],  *be1 = (const float*)d_in[5];
    const float *W2 = (const float*)d_in[6],  *b2  = (const float*)d_in[7];
    const float *Wmu= (const float*)d_in[8],  *bmu = (const float*)d_in[9];
    const float *Wlv= (const float*)d_in[10], *blv = (const float*)d_in[11];
    const float *dW1= (const float*)d_in[12], *db1 = (const float*)d_in[13];
    const float *dW2= (const float*)d_in[14], *db2 = (const float*)d_in[15];
    const float *dW3= (const float*)d_in[16], *db3 = (const float*)d_in[17];

    const int* nidx = hei;
    const int* eidx = hei + N_PINS;

    float* out    = (float*)d_out;
    float* out_z  = out;
    float* out_m  = out + N_NODES;
    float* out_lv = out + 2 * N_NODES;

    const int TB = 256;
    const int pins_blocks   = (N_PINS + TB - 1) / TB;      // 6250
    const int gather_blocks = (N_EDGES * 32) / TB;         // 12500 (warp/row)
    const int mm_blocks     = N_NODES / 32;                // 3125
    const int dec_blocks    = (N_NODES + 3) / 4;
    const int n_blocks      = (N_NODES + TB - 1) / TB;

    // CSR build
    zero_cnt_kernel<<<NB, TB>>>();
    hist_kernel<<<pins_blocks, TB>>>(nidx, eidx);
    scan1_kernel<<<NB, TB>>>();
    scan2_kernel<<<1, 512>>>();
    scan3_kernel<<<NB, TB>>>();
    fill_kernel<<<pins_blocks, TB>>>(nidx, eidx);

    // layer 1: edge-gather(x fp32 -> g_HE fp16/32w) -> fused node-gather+@W1+LN+leaky -> g_H fp16
    gather_edge_x_kernel<<<gather_blocks, TB>>>(x);
    fused_mm_ln_kernel<<<mm_blocks, TB>>>(W1, b1, g1, be1);

    // layer 2: edge-gather(g_H fp16 -> g_HE fp16/64w) -> fused node-gather+@W2+leaky -> g_H fp16
    gather_edge_h_kernel<<<gather_blocks, TB>>>();
    fused_mm_leaky_kernel<<<mm_blocks, TB>>>(W2, b2);

    // layer 3: edge-gather(g_H) -> fused node-gather + dual matmul -> g_MU, out_lv (fp32)
    gather_edge_h_kernel<<<gather_blocks, TB>>>();
    fused_mm_dual_kernel<<<mm_blocks, TB>>>(Wmu, bmu, Wlv, blv, out_lv);

    // decode(z = mu) once; z_orth == mu_orth in eval mode
    decode_kernel<<<dec_blocks, 128>>>(dW1, db1, dW2, db2, dW3, db3);
    norm_write_kernel<<<n_blocks, TB>>>(out_z, out_m);
}